// round 8
// baseline (speedup 1.0000x reference)
#include <cuda_runtime.h>

// LengthRegulator, fused single-wave kernel.
// b=16, t_x=1024, d=256, out_len=7168.
// out[b, j, :] = x[b, phoneme(j), :]; lengths[b] = sum(rep[b,:]).
// grid = (56, 16) = 896 blocks -> all resident in one wave (8 blocks/SM cap).

#define B_DIM   16
#define TX      1024
#define D_DIM   256
#define OUT_LEN 7168
#define D_VEC   (D_DIM / 4)      // 64 float4 per row
#define FPT     8                // frames per 64-lane group per gather batch
#define FRAMES_PER_BLK 128       // 4 gather batches of 32 frames
#define NBATCH  4
#define NWARP   8                // 256 threads

__global__ void __launch_bounds__(256)
fused_kernel(const float4* __restrict__ x4,
             const int*    __restrict__ rep,
             float*        __restrict__ out,
             int out_size) {
    __shared__ int s_cum[TX];
    __shared__ int s_ph[FRAMES_PER_BLK];
    __shared__ int warp_tot[NWARP];

    const int b    = blockIdx.y;
    const int base = blockIdx.x * FRAMES_PER_BLK;
    const int tid  = threadIdx.x;
    const int lane = tid & 31;
    const int wid  = tid >> 5;

    // ---- in-block scan of rep[b, :] (each thread owns 4 consecutive) ----
    const int4 r = ((const int4*)(rep + b * TX))[tid];
    const int p0 = r.x;
    const int p1 = p0 + r.y;
    const int p2 = p1 + r.z;
    const int p3 = p2 + r.w;                 // per-thread inclusive sums

    int ws = p3;                             // warp inclusive scan of p3
    #pragma unroll
    for (int off = 1; off < 32; off <<= 1) {
        int n = __shfl_up_sync(0xFFFFFFFFu, ws, off);
        if (lane >= off) ws += n;
    }
    if (lane == 31) warp_tot[wid] = ws;
    __syncthreads();

    if (wid == 0 && lane < NWARP) {          // scan the 8 warp totals
        int w = warp_tot[lane];
        #pragma unroll
        for (int off = 1; off < NWARP; off <<= 1) {
            int n = __shfl_up_sync(0xFFu, w, off);
            if (lane >= off) w += n;
        }
        warp_tot[lane] = w;                  // inclusive prefix
    }
    __syncthreads();

    const int off0 = (wid > 0 ? warp_tot[wid - 1] : 0) + (ws - p3);
    s_cum[4 * tid + 0] = off0 + p0;
    s_cum[4 * tid + 1] = off0 + p1;
    s_cum[4 * tid + 2] = off0 + p2;
    s_cum[4 * tid + 3] = off0 + p3;
    __syncthreads();

    const int total = s_cum[TX - 1];

    // lengths[b] (one block per batch writes it)
    if (blockIdx.x == 0 && tid == 0) {
        const size_t main_elems = (size_t)B_DIM * OUT_LEN * D_DIM;
        if ((size_t)out_size > main_elems)
            out[main_elems + b] = (float)total;
    }

    // ---- 128 binary searches: frame -> phoneme ----
    if (tid < FRAMES_PER_BLK) {
        const int j = base + tid;
        int ph = -1;
        if (j < total) {
            // lower_bound: first i with s_cum[i] > j; 11 iters for width 1024.
            int lo = 0, hi = TX;
            #pragma unroll
            for (int it = 0; it < 11; ++it) {
                int mid = (lo + hi) >> 1;
                if (s_cum[mid] > j) hi = mid; else lo = mid + 1;
            }
            ph = lo;
        }
        s_ph[tid] = ph;
    }
    __syncthreads();

    // ---- gather + store: 4 groups of 64 lanes, FPT frames per batch, ------
    // ---- NBATCH batches. Independent loads -> MLP = FPT. ------------------
    const int group = tid >> 6;              // 0..3
    const int gl    = tid & 63;
    float4* out4 = (float4*)out;

    #pragma unroll
    for (int batch = 0; batch < NBATCH; ++batch) {
        const int f0 = group * (FRAMES_PER_BLK / 4) + batch * FPT;

        int ph[FPT];
        #pragma unroll
        for (int k = 0; k < FPT; ++k) ph[k] = s_ph[f0 + k];

        float4 v[FPT];
        #pragma unroll
        for (int k = 0; k < FPT; ++k) {
            v[k] = make_float4(0.f, 0.f, 0.f, 0.f);
            if (ph[k] >= 0)
                v[k] = x4[((size_t)b * TX + ph[k]) * D_VEC + gl];
        }

        #pragma unroll
        for (int k = 0; k < FPT; ++k)
            out4[((size_t)b * OUT_LEN + base + f0 + k) * D_VEC + gl] = v[k];
    }
}

// ---------------------------------------------------------------------------
extern "C" void kernel_launch(void* const* d_in, const int* in_sizes, int n_in,
                              void* d_out, int out_size) {
    const float* x   = (const float*)d_in[0];   // (16,1024,256) fp32
    const int*   rep = (const int*)d_in[1];     // (16,1024) int32
    float* out = (float*)d_out;

    dim3 grid(OUT_LEN / FRAMES_PER_BLK, B_DIM); // (56, 16) = 896 blocks
    fused_kernel<<<grid, 256>>>((const float4*)x, rep, out, out_size);
}

// round 9
// speedup vs baseline: 1.0145x; 1.0145x over previous
#include <cuda_runtime.h>

// LengthRegulator, fused SCATTER kernel.
// b=16, t_x=1024, d=256, out_len=7168.
// out[b, j, :] = x[b, phoneme(j), :]; lengths[b] = sum(rep[b,:]).
//
// Scatter form: each 64-lane group loads a phoneme row once and stores it
// dur times (consecutive coalesced 1KB rows). Tail frames [total, out_len)
// are zero-filled by dedicated blocks. No binary searches.

#define B_DIM   16
#define TX      1024
#define D_DIM   256
#define OUT_LEN 7168
#define D_VEC   (D_DIM / 4)      // 64 float4 per row
#define NWARP   8                // 256 threads

#define PH_PER_GROUP 4           // phonemes handled by each 64-lane group
#define PH_PER_BLK   16          // 4 groups * 4
#define SCAT_BLKS    (TX / PH_PER_BLK)        // 64 scatter blocks per batch
#define ZERO_BLKS    64
#define ZFR          (OUT_LEN / ZERO_BLKS)    // 112 frames per zero block

__global__ void __launch_bounds__(256)
fused_scatter_kernel(const float4* __restrict__ x4,
                     const int*    __restrict__ rep,
                     float*        __restrict__ out,
                     int out_size) {
    __shared__ int s_cum[TX];
    __shared__ int warp_tot[NWARP];

    const int b    = blockIdx.y;
    const int tid  = threadIdx.x;
    const int lane = tid & 31;
    const int wid  = tid >> 5;

    // ---- in-block scan of rep[b, :] (each thread owns 4 consecutive) ----
    const int4 r = ((const int4*)(rep + b * TX))[tid];
    const int p0 = r.x;
    const int p1 = p0 + r.y;
    const int p2 = p1 + r.z;
    const int p3 = p2 + r.w;                 // per-thread inclusive sums

    int ws = p3;                             // warp inclusive scan of p3
    #pragma unroll
    for (int off = 1; off < 32; off <<= 1) {
        int n = __shfl_up_sync(0xFFFFFFFFu, ws, off);
        if (lane >= off) ws += n;
    }
    if (lane == 31) warp_tot[wid] = ws;
    __syncthreads();

    if (wid == 0 && lane < NWARP) {          // scan the 8 warp totals
        int w = warp_tot[lane];
        #pragma unroll
        for (int off = 1; off < NWARP; off <<= 1) {
            int n = __shfl_up_sync(0xFFu, w, off);
            if (lane >= off) w += n;
        }
        warp_tot[lane] = w;                  // inclusive prefix
    }
    __syncthreads();

    const int off0 = (wid > 0 ? warp_tot[wid - 1] : 0) + (ws - p3);
    s_cum[4 * tid + 0] = off0 + p0;
    s_cum[4 * tid + 1] = off0 + p1;
    s_cum[4 * tid + 2] = off0 + p2;
    s_cum[4 * tid + 3] = off0 + p3;
    __syncthreads();

    const int total = s_cum[TX - 1];
    float4* out4 = (float4*)out;

    // lengths[b] (one block per batch writes it)
    if (blockIdx.x == 0 && tid == 0) {
        const size_t main_elems = (size_t)B_DIM * OUT_LEN * D_DIM;
        if ((size_t)out_size > main_elems)
            out[main_elems + b] = (float)total;
    }

    const int group = tid >> 6;              // 0..3
    const int gl    = tid & 63;

    if (blockIdx.x < SCAT_BLKS) {
        // ---- scatter: each group expands PH_PER_GROUP phonemes ----
        const int ph_base = blockIdx.x * PH_PER_BLK + group * PH_PER_GROUP;

        // span bounds (broadcast smem reads; uniform per group)
        int s[PH_PER_GROUP], e[PH_PER_GROUP];
        #pragma unroll
        for (int q = 0; q < PH_PER_GROUP; ++q) {
            const int p = ph_base + q;
            e[q] = s_cum[p];
            s[q] = (p > 0) ? s_cum[p - 1] : 0;
        }

        // batch the row loads first (independent -> MLP)
        float4 row[PH_PER_GROUP];
        #pragma unroll
        for (int q = 0; q < PH_PER_GROUP; ++q)
            if (e[q] > s[q])
                row[q] = x4[((size_t)b * TX + ph_base + q) * D_VEC + gl];

        // store each row dur times to consecutive output rows
        #pragma unroll
        for (int q = 0; q < PH_PER_GROUP; ++q)
            for (int j = s[q]; j < e[q]; ++j)
                out4[((size_t)b * OUT_LEN + j) * D_VEC + gl] = row[q];
    } else {
        // ---- zero-fill the tail [total, OUT_LEN) within this block's range --
        const int zb = (blockIdx.x - SCAT_BLKS) * ZFR;
        const int ze = zb + ZFR;
        int j0 = zb + group;
        // advance to first row >= total (branch-free start)
        if (j0 < total) j0 += ((total - j0 + 3) >> 2) << 2;
        const float4 zero = make_float4(0.f, 0.f, 0.f, 0.f);
        for (int j = j0; j < ze; j += 4)
            out4[((size_t)b * OUT_LEN + j) * D_VEC + gl] = zero;
    }
}

// ---------------------------------------------------------------------------
extern "C" void kernel_launch(void* const* d_in, const int* in_sizes, int n_in,
                              void* d_out, int out_size) {
    const float* x   = (const float*)d_in[0];   // (16,1024,256) fp32
    const int*   rep = (const int*)d_in[1];     // (16,1024) int32
    float* out = (float*)d_out;

    dim3 grid(SCAT_BLKS + ZERO_BLKS, B_DIM);    // (128, 16) = 2048 blocks
    fused_scatter_kernel<<<grid, 256>>>((const float4*)x, rep, out, out_size);
}

// round 10
// speedup vs baseline: 1.1816x; 1.1647x over previous
#include <cuda_runtime.h>

// LengthRegulator, fused SCATTER kernel with streaming stores.
// b=16, t_x=1024, d=256, out_len=7168.
// out[b, j, :] = x[b, phoneme(j), :]; lengths[b] = sum(rep[b,:]).
//
// Scatter form: each 64-lane group loads a phoneme row once and stores it
// dur times (consecutive coalesced 1KB rows). Tail frames [total, out_len)
// are zero-filled by dedicated blocks. All output stores use __stcs
// (streaming, evict-first) so L2 dirty-writeback overlaps the kernel.

#define B_DIM   16
#define TX      1024
#define D_DIM   256
#define OUT_LEN 7168
#define D_VEC   (D_DIM / 4)      // 64 float4 per row
#define NWARP   8                // 256 threads

#define PH_PER_GROUP 4           // phonemes handled by each 64-lane group
#define PH_PER_BLK   16          // 4 groups * 4
#define SCAT_BLKS    (TX / PH_PER_BLK)        // 64 scatter blocks per batch
#define ZERO_BLKS    64
#define ZFR          (OUT_LEN / ZERO_BLKS)    // 112 frames per zero block

__global__ void __launch_bounds__(256)
fused_scatter_kernel(const float4* __restrict__ x4,
                     const int*    __restrict__ rep,
                     float*        __restrict__ out,
                     int out_size) {
    __shared__ int s_cum[TX];
    __shared__ int warp_tot[NWARP];

    const int b    = blockIdx.y;
    const int tid  = threadIdx.x;
    const int lane = tid & 31;
    const int wid  = tid >> 5;

    // ---- in-block scan of rep[b, :] (each thread owns 4 consecutive) ----
    const int4 r = ((const int4*)(rep + b * TX))[tid];
    const int p0 = r.x;
    const int p1 = p0 + r.y;
    const int p2 = p1 + r.z;
    const int p3 = p2 + r.w;                 // per-thread inclusive sums

    int ws = p3;                             // warp inclusive scan of p3
    #pragma unroll
    for (int off = 1; off < 32; off <<= 1) {
        int n = __shfl_up_sync(0xFFFFFFFFu, ws, off);
        if (lane >= off) ws += n;
    }
    if (lane == 31) warp_tot[wid] = ws;
    __syncthreads();

    if (wid == 0 && lane < NWARP) {          // scan the 8 warp totals
        int w = warp_tot[lane];
        #pragma unroll
        for (int off = 1; off < NWARP; off <<= 1) {
            int n = __shfl_up_sync(0xFFu, w, off);
            if (lane >= off) w += n;
        }
        warp_tot[lane] = w;                  // inclusive prefix
    }
    __syncthreads();

    const int off0 = (wid > 0 ? warp_tot[wid - 1] : 0) + (ws - p3);
    s_cum[4 * tid + 0] = off0 + p0;
    s_cum[4 * tid + 1] = off0 + p1;
    s_cum[4 * tid + 2] = off0 + p2;
    s_cum[4 * tid + 3] = off0 + p3;
    __syncthreads();

    const int total = s_cum[TX - 1];
    float4* out4 = (float4*)out;

    // lengths[b] (one block per batch writes it)
    if (blockIdx.x == 0 && tid == 0) {
        const size_t main_elems = (size_t)B_DIM * OUT_LEN * D_DIM;
        if ((size_t)out_size > main_elems)
            out[main_elems + b] = (float)total;
    }

    const int group = tid >> 6;              // 0..3
    const int gl    = tid & 63;

    if (blockIdx.x < SCAT_BLKS) {
        // ---- scatter: each group expands PH_PER_GROUP phonemes ----
        const int ph_base = blockIdx.x * PH_PER_BLK + group * PH_PER_GROUP;

        // span bounds (broadcast smem reads; uniform per group)
        int s[PH_PER_GROUP], e[PH_PER_GROUP];
        #pragma unroll
        for (int q = 0; q < PH_PER_GROUP; ++q) {
            const int p = ph_base + q;
            e[q] = s_cum[p];
            s[q] = (p > 0) ? s_cum[p - 1] : 0;
        }

        // batch the row loads first (independent -> MLP)
        float4 row[PH_PER_GROUP];
        #pragma unroll
        for (int q = 0; q < PH_PER_GROUP; ++q)
            if (e[q] > s[q])
                row[q] = x4[((size_t)b * TX + ph_base + q) * D_VEC + gl];

        // store each row dur times to consecutive output rows (streaming)
        #pragma unroll
        for (int q = 0; q < PH_PER_GROUP; ++q)
            for (int j = s[q]; j < e[q]; ++j)
                __stcs(&out4[((size_t)b * OUT_LEN + j) * D_VEC + gl], row[q]);
    } else {
        // ---- zero-fill the tail [total, OUT_LEN) within this block's range --
        const int zb = (blockIdx.x - SCAT_BLKS) * ZFR;
        const int ze = zb + ZFR;
        int j0 = zb + group;
        // advance to first row >= total (branch-free start)
        if (j0 < total) j0 += ((total - j0 + 3) >> 2) << 2;
        const float4 zero = make_float4(0.f, 0.f, 0.f, 0.f);
        for (int j = j0; j < ze; j += 4)
            __stcs(&out4[((size_t)b * OUT_LEN + j) * D_VEC + gl], zero);
    }
}

// ---------------------------------------------------------------------------
extern "C" void kernel_launch(void* const* d_in, const int* in_sizes, int n_in,
                              void* d_out, int out_size) {
    const float* x   = (const float*)d_in[0];   // (16,1024,256) fp32
    const int*   rep = (const int*)d_in[1];     // (16,1024) int32
    float* out = (float*)d_out;

    dim3 grid(SCAT_BLKS + ZERO_BLKS, B_DIM);    // (128, 16) = 2048 blocks
    fused_scatter_kernel<<<grid, 256>>>((const float4*)x, rep, out, out_size);
}

// round 11
// speedup vs baseline: 1.2548x; 1.0620x over previous
#include <cuda_runtime.h>

// LengthRegulator, fused gather kernel (R6 structure) + streaming stores (R9).
// b=16, t_x=1024, d=256, out_len=7168.
// out[b, j, :] = x[b, phoneme(j), :]; lengths[b] = sum(rep[b,:]).

#define B_DIM   16
#define TX      1024
#define D_DIM   256
#define OUT_LEN 7168
#define D_VEC   (D_DIM / 4)      // 64 float4 per row
#define FPT     8                // frames per 64-lane group per batch
#define FRAMES_PER_BLK 64        // 4 groups * FPT * 2 batches
#define NWARP   8                // 256 threads

__global__ void __launch_bounds__(256)
fused_kernel(const float4* __restrict__ x4,
             const int*    __restrict__ rep,
             float*        __restrict__ out,
             int out_size) {
    __shared__ int s_cum[TX];
    __shared__ int s_ph[FRAMES_PER_BLK];
    __shared__ int warp_tot[NWARP];

    const int b    = blockIdx.y;
    const int base = blockIdx.x * FRAMES_PER_BLK;
    const int tid  = threadIdx.x;
    const int lane = tid & 31;
    const int wid  = tid >> 5;

    // ---- in-block scan of rep[b, :] (each thread owns 4 consecutive) ----
    const int4 r = ((const int4*)(rep + b * TX))[tid];
    const int p0 = r.x;
    const int p1 = p0 + r.y;
    const int p2 = p1 + r.z;
    const int p3 = p2 + r.w;                 // per-thread inclusive sums

    int ws = p3;                             // warp inclusive scan of p3
    #pragma unroll
    for (int off = 1; off < 32; off <<= 1) {
        int n = __shfl_up_sync(0xFFFFFFFFu, ws, off);
        if (lane >= off) ws += n;
    }
    if (lane == 31) warp_tot[wid] = ws;
    __syncthreads();

    if (wid == 0 && lane < NWARP) {          // scan the 8 warp totals
        int w = warp_tot[lane];
        #pragma unroll
        for (int off = 1; off < NWARP; off <<= 1) {
            int n = __shfl_up_sync(0xFFu, w, off);
            if (lane >= off) w += n;
        }
        warp_tot[lane] = w;                  // inclusive prefix
    }
    __syncthreads();

    const int off0 = (wid > 0 ? warp_tot[wid - 1] : 0) + (ws - p3);
    s_cum[4 * tid + 0] = off0 + p0;
    s_cum[4 * tid + 1] = off0 + p1;
    s_cum[4 * tid + 2] = off0 + p2;
    s_cum[4 * tid + 3] = off0 + p3;
    __syncthreads();

    const int total = s_cum[TX - 1];

    // lengths[b] (one block per batch writes it)
    if (blockIdx.x == 0 && tid == 0) {
        const size_t main_elems = (size_t)B_DIM * OUT_LEN * D_DIM;
        if ((size_t)out_size > main_elems)
            out[main_elems + b] = (float)total;
    }

    // ---- 64 binary searches: frame -> phoneme ----
    if (tid < FRAMES_PER_BLK) {
        const int j = base + tid;
        int ph = -1;
        if (j < total) {
            // lower_bound: first i with s_cum[i] > j; 11 iters for width 1024.
            int lo = 0, hi = TX;
            #pragma unroll
            for (int it = 0; it < 11; ++it) {
                int mid = (lo + hi) >> 1;
                if (s_cum[mid] > j) hi = mid; else lo = mid + 1;
            }
            ph = lo;
        }
        s_ph[tid] = ph;
    }
    __syncthreads();

    // ---- gather + store: 4 groups of 64 lanes, 16 frames each (2 x FPT=8) --
    const int group = tid >> 6;              // 0..3
    const int gl    = tid & 63;
    float4* out4 = (float4*)out;

    #pragma unroll
    for (int batch = 0; batch < 2; ++batch) {
        const int f0 = group * 16 + batch * FPT;   // frame offset in block

        int ph[FPT];
        #pragma unroll
        for (int k = 0; k < FPT; ++k) ph[k] = s_ph[f0 + k];

        float4 v[FPT];
        #pragma unroll
        for (int k = 0; k < FPT; ++k) {
            v[k] = make_float4(0.f, 0.f, 0.f, 0.f);
            if (ph[k] >= 0)
                v[k] = x4[((size_t)b * TX + ph[k]) * D_VEC + gl];
        }

        #pragma unroll
        for (int k = 0; k < FPT; ++k)
            __stcs(&out4[((size_t)b * OUT_LEN + base + f0 + k) * D_VEC + gl],
                   v[k]);
    }
}

// ---------------------------------------------------------------------------
extern "C" void kernel_launch(void* const* d_in, const int* in_sizes, int n_in,
                              void* d_out, int out_size) {
    const float* x   = (const float*)d_in[0];   // (16,1024,256) fp32
    const int*   rep = (const int*)d_in[1];     // (16,1024) int32
    float* out = (float*)d_out;

    dim3 grid(OUT_LEN / FRAMES_PER_BLK, B_DIM); // (112, 16) = 1792 blocks
    fused_kernel<<<grid, 256>>>((const float4*)x, rep, out, out_size);
}